// round 12
// baseline (speedup 1.0000x reference)
#include <cuda_runtime.h>
#include <math.h>

#define TSEQ 100
#define BATCH 64
#define HGRU  128
#define G3    384   // 3*H

// ---------------- tf32 helpers ----------------
__device__ __forceinline__ unsigned f2tf32(float x) {
    unsigned u;
    asm("cvt.rna.tf32.f32 %0, %1;" : "=r"(u) : "f"(x));
    return u;
}

__device__ __forceinline__ void mma_tf32v(float* d, const unsigned* a, const unsigned* b) {
    asm volatile(
        "mma.sync.aligned.m16n8k8.row.col.f32.tf32.tf32.f32 "
        "{%0,%1,%2,%3}, {%4,%5,%6,%7}, {%8,%9}, {%0,%1,%2,%3};"
        : "+f"(d[0]), "+f"(d[1]), "+f"(d[2]), "+f"(d[3])
        : "r"(a[0]), "r"(a[1]), "r"(a[2]), "r"(a[3]),
          "r"(b[0]), "r"(b[1]));
}

// cp.async helpers
#define CPA(dst, src, sz) \
    asm volatile("cp.async.ca.shared.global [%0], [%1], 16, %2;" :: "r"(dst), "l"(src), "r"(sz))
#define CPC()  asm volatile("cp.async.commit_group;")
#define CPW0() asm volatile("cp.async.wait_group 0;")
#define CPW1() asm volatile("cp.async.wait_group 1;")

// ---------------- scratch (static __device__, no allocation) ----------------
__device__ float g_e[6400 * 128];      // embedded input, tf32-rounded
__device__ float g_gi[6400 * 768];     // gi for both directions (fp32)
__device__ float g_y[6400 * 256];      // layer output, tf32-rounded
__device__ float g_fcin[64 * 1024];    // [enc_h(512) | dec_h(512)], full fp32
__device__ float g_fcin_tf[64 * 1024]; // tf32-rounded copy for dec-l0 GEMM
__device__ float g_wt[884736];         // tf32 Wih: enc0@0, enc1@98304, dec0@294912, dec1@688128
__device__ float g_recw[2560000];      // tf32 recW

// ---------------- fused tf32 rounding of all 5 weight regions (one launch) ----------------
// float4 units: 24576 | 49152 | 98304 | 49152 | 640000, prefix: 24576,73728,172032,221184,861184
__global__ void cvt_all(const float4* __restrict__ s0, float4* __restrict__ d0,
                        const float4* __restrict__ s1, float4* __restrict__ d1,
                        const float4* __restrict__ s2, float4* __restrict__ d2,
                        const float4* __restrict__ s3, float4* __restrict__ d3,
                        const float4* __restrict__ s4, float4* __restrict__ d4) {
    int i = blockIdx.x * 256 + threadIdx.x;
    const float4* s; float4* d; int off;
    if      (i < 24576)  { s = s0; d = d0; off = i; }
    else if (i < 73728)  { s = s1; d = d1; off = i - 24576; }
    else if (i < 172032) { s = s2; d = d2; off = i - 73728; }
    else if (i < 221184) { s = s3; d = d3; off = i - 172032; }
    else if (i < 861184) { s = s4; d = d4; off = i - 221184; }
    else return;
    float4 v = s[off];
    v.x = __uint_as_float(f2tf32(v.x));
    v.y = __uint_as_float(f2tf32(v.y));
    v.z = __uint_as_float(f2tf32(v.z));
    v.w = __uint_as_float(f2tf32(v.w));
    d[off] = v;
}

// ---------------- elementwise tf32 rounding (fcin only) ----------------
__global__ void cvt_kernel(const float* __restrict__ src, float* __restrict__ dst, int n) {
    for (int i = blockIdx.x * 256 + threadIdx.x; i < n; i += gridDim.x * 256)
        dst[i] = __uint_as_float(f2tf32(src[i]));
}

// ---------------- embedding gather (writes tf32-rounded) ----------------
__global__ void embed_kernel(const int* __restrict__ x,
                             const float* __restrict__ emb,
                             float* __restrict__ e) {
    int row = blockIdx.x;                 // b*T + t
    int v = x[row];
    if (v > 9999) v = 9999;
    if (v < 0)    v = 0;
    e[row * 128 + threadIdx.x] = __uint_as_float(f2tf32(emb[v * 128 + threadIdx.x]));
}

// ---------------- classifier head GEMV: warp per output ----------------
__global__ void fc_kernel(const float* __restrict__ fcin,   // (64, 1024)
                          const float* __restrict__ W,      // (20, 1024)
                          const float* __restrict__ bias,   // (20)
                          float* __restrict__ out) {        // (64, 20)
    int wid  = (blockIdx.x * blockDim.x + threadIdx.x) >> 5;
    int lane = threadIdx.x & 31;
    if (wid >= 64 * 20) return;
    int m = wid / 20, n = wid % 20;
    const float4* a = (const float4*)(fcin + m * 1024);
    const float4* w = (const float4*)(W    + n * 1024);
    float s = 0.f;
#pragma unroll
    for (int i = lane; i < 256; i += 32) {
        float4 x = a[i], y = w[i];
        s += x.x * y.x + x.y * y.y + x.z * y.z + x.w * y.w;
    }
#pragma unroll
    for (int o = 16; o; o >>= 1) s += __shfl_xor_sync(0xffffffffu, s, o);
    if (lane == 0) out[m * 20 + n] = s + bias[n];
}

// ---------------- GRU recurrence: split-K over 768 threads, packed f32x2 FMA ----------------
// Thread T<384: k in [0,64) of column T.  Thread T>=384: k in [64,128) of column T-384.
// Partials combined in the gate tail: gh_c = sp[c] + sp[c+384] + bh_c.
// h loads are compiler-visible shared reads (cannot be hoisted across __syncthreads()).
__global__ void __launch_bounds__(768, 1)
gru_kernel(const float* __restrict__ gi_base, int rb, int rt,
           const float* __restrict__ Whh,   // (2, 384, 128)
           const float* __restrict__ bhh,   // (2, 384)
           float* __restrict__ y,           // (B, T, 256), written tf32-rounded
           float* __restrict__ hfin) {
    __shared__ __align__(16) float sh[128];
    __shared__ float sp[768];
    __shared__ float sgi[G3];

    int T    = threadIdx.x;              // 0..767
    int half = (T >= G3) ? 1 : 0;
    int col  = T - half * G3;            // 0..383
    int b    = blockIdx.x;
    int dir  = blockIdx.y;

    const float* gi = gi_base + dir * G3;

    // this (column, k-half)'s weights: 64 floats = 32 packed f32x2
    unsigned long long w2[32];
    const unsigned long long* Wrow =
        (const unsigned long long*)(Whh + (size_t)(dir * G3 + col) * HGRU + half * 64);
#pragma unroll
    for (int kk = 0; kk < 32; kk++) w2[kk] = Wrow[kk];

    // tail biases
    float bh0 = 0.f, bh1 = 0.f, bh2 = 0.f;
    if (T < HGRU) {
        bh0 = bhh[dir * G3 + T];
        bh1 = bhh[dir * G3 + T + 128];
        bh2 = bhh[dir * G3 + T + 256];
    }

    if (T < HGRU) sh[T] = 0.f;
    __syncthreads();

    const ulonglong2* sh2 = (const ulonglong2*)sh + half * 16;   // 16 x 16B per half

    int tt_first = dir ? (TSEQ - 1) : 0;
    float gval = (T < G3) ? gi[(b * rb + tt_first * rt) * 768 + T] : 0.f;

    for (int t = 0; t < TSEQ; t++) {
        int tt = dir ? (TSEQ - 1 - t) : t;

        // prefetch next step's gi — consumed a full step later
        float gnext = 0.f;
        if (T < G3 && t + 1 < TSEQ) {
            int ttn = dir ? (TSEQ - 2 - t) : (t + 1);
            gnext = gi[(b * rb + ttn * rt) * 768 + T];
        }

        unsigned long long acc0 = 0ULL, acc1 = 0ULL, acc2 = 0ULL, acc3 = 0ULL;
#pragma unroll
        for (int kk = 0; kk < 16; kk += 2) {
            ulonglong2 ha = sh2[kk];
            ulonglong2 hb = sh2[kk + 1];
            asm("fma.rn.f32x2 %0, %1, %2, %0;" : "+l"(acc0) : "l"(w2[2 * kk + 0]), "l"(ha.x));
            asm("fma.rn.f32x2 %0, %1, %2, %0;" : "+l"(acc1) : "l"(w2[2 * kk + 1]), "l"(ha.y));
            asm("fma.rn.f32x2 %0, %1, %2, %0;" : "+l"(acc2) : "l"(w2[2 * kk + 2]), "l"(hb.x));
            asm("fma.rn.f32x2 %0, %1, %2, %0;" : "+l"(acc3) : "l"(w2[2 * kk + 3]), "l"(hb.y));
        }
        asm("add.rn.f32x2 %0, %0, %1;" : "+l"(acc0) : "l"(acc1));
        asm("add.rn.f32x2 %0, %0, %1;" : "+l"(acc2) : "l"(acc3));
        asm("add.rn.f32x2 %0, %0, %1;" : "+l"(acc0) : "l"(acc2));
        float lo, hi;
        asm("mov.b64 {%0,%1}, %2;" : "=f"(lo), "=f"(hi) : "l"(acc0));

        sp[T] = lo + hi;
        if (T < G3) sgi[T] = gval;
        __syncthreads();

        if (T < HGRU) {
            float ghr = sp[T]       + sp[T + 384] + bh0;
            float ghz = sp[T + 128] + sp[T + 512] + bh1;
            float ghn = sp[T + 256] + sp[T + 640] + bh2;
            float r = __fdividef(1.f, 1.f + __expf(-(sgi[T]       + ghr)));
            float z = __fdividef(1.f, 1.f + __expf(-(sgi[T + 128] + ghz)));
            float nx = sgi[T + 256] + r * ghn;
            float et = __expf(-2.f * nx);
            float n  = __fdividef(1.f - et, 1.f + et);   // tanh(nx)
            float hn = n + z * (sh[T] - n);
            sh[T] = hn;
            y[(b * TSEQ + tt) * 256 + dir * HGRU + T] = __uint_as_float(f2tf32(hn));
        }
        __syncthreads();

        gval = gnext;
    }
    if (T < HGRU) hfin[b * 1024 + dir * HGRU + T] = sh[T];
}

// ---------------- tf32 MMA GEMM, cp.async double-buffered ----------------
// C[M,N] = A[M,K](lda) * W[N,K]^T + bias. Inputs MUST be pre-rounded to tf32.
// 128x128 CTA tile, 8 warps (4M x 2N), warp tile 32x64, K-chunk 32, 2-stage pipeline.
#define MMA_SMEM (2 * 128 * 36 * 4 * 2)   // 73728 B
__global__ void __launch_bounds__(256, 2)
mma_tn(const float* __restrict__ A, int lda,
       const float* __restrict__ W,     // (N, K)
       const float* __restrict__ bias,  // (N)
       float* __restrict__ C,
       int M, int N, int K) {
    extern __shared__ float smem[];
    float* As = smem;                    // [2][128][36]
    float* Bs = smem + 2 * 128 * 36;

    int t    = threadIdx.x;
    int lane = t & 31;
    int warp = t >> 5;
    int m0 = blockIdx.y * 128;
    int n0 = blockIdx.x * 128;
    int wm = (warp & 3) * 32;
    int wn = (warp >> 2) * 64;
    int r  = lane >> 2;       // 0..7
    int c  = lane & 3;        // 0..3

    unsigned sbaseA = (unsigned)__cvta_generic_to_shared(As);
    unsigned sbaseB = (unsigned)__cvta_generic_to_shared(Bs);

    float acc[2][8][4];
#pragma unroll
    for (int mf = 0; mf < 2; mf++)
#pragma unroll
        for (int nf = 0; nf < 8; nf++)
#pragma unroll
            for (int i = 0; i < 4; i++) acc[mf][nf][i] = 0.f;

    int nch = K >> 5;    // K/32 chunks

    auto stage = [&](int buf, int k0) {
#pragma unroll
        for (int i = 0; i < 4; i++) {
            int idx = i * 256 + t;
            int row = idx >> 3;
            int c4  = (idx & 7) * 4;
            unsigned off = ((unsigned)(buf * 128 + row) * 36 + c4) * 4;
            CPA(sbaseA + off, &A[(size_t)(m0 + row) * lda + k0 + c4], (m0 + row < M) ? 16 : 0);
            CPA(sbaseB + off, &W[(size_t)(n0 + row) * K   + k0 + c4], (n0 + row < N) ? 16 : 0);
        }
    };

    auto compute = [&](int buf) {
        const float* Ab = As + buf * 128 * 36;
        const float* Bb = Bs + buf * 128 * 36;
#pragma unroll
        for (int ks = 0; ks < 4; ks++) {
            int kb = ks * 8;
            unsigned a[2][4];
#pragma unroll
            for (int mf = 0; mf < 2; mf++) {
                int mr = wm + mf * 16 + r;
                a[mf][0] = __float_as_uint(Ab[(mr    ) * 36 + kb + c]);
                a[mf][1] = __float_as_uint(Ab[(mr + 8) * 36 + kb + c]);
                a[mf][2] = __float_as_uint(Ab[(mr    ) * 36 + kb + c + 4]);
                a[mf][3] = __float_as_uint(Ab[(mr + 8) * 36 + kb + c + 4]);
            }
#pragma unroll
            for (int nf = 0; nf < 8; nf++) {
                int nr = wn + nf * 8 + r;
                unsigned b[2];
                b[0] = __float_as_uint(Bb[nr * 36 + kb + c]);
                b[1] = __float_as_uint(Bb[nr * 36 + kb + c + 4]);
                mma_tf32v(acc[0][nf], a[0], b);
                mma_tf32v(acc[1][nf], a[1], b);
            }
        }
    };

    // prologue: 2 chunks in flight
    stage(0, 0);  CPC();
    stage(1, 32); CPC();

    for (int ci = 0; ci < nch; ci++) {
        if (ci < nch - 1) { CPW1(); } else { CPW0(); }
        __syncthreads();
        compute(ci & 1);
        __syncthreads();
        if (ci + 2 < nch) { stage(ci & 1, (ci + 2) * 32); CPC(); }
    }

    // epilogue
#pragma unroll
    for (int mf = 0; mf < 2; mf++) {
#pragma unroll
        for (int nf = 0; nf < 8; nf++) {
            int n = n0 + wn + nf * 8 + 2 * c;
            if (n >= N) continue;
            float bv0 = bias[n];
            float bv1 = bias[n + 1];
            int m = m0 + wm + mf * 16 + r;
            if (m < M) {
                *(float2*)&C[(size_t)m * N + n] =
                    make_float2(acc[mf][nf][0] + bv0, acc[mf][nf][1] + bv1);
            }
            if (m + 8 < M) {
                *(float2*)&C[(size_t)(m + 8) * N + n] =
                    make_float2(acc[mf][nf][2] + bv0, acc[mf][nf][3] + bv1);
            }
        }
    }
}

// ---------------- driver ----------------
extern "C" void kernel_launch(void* const* d_in, const int* in_sizes, int n_in,
                              void* d_out, int out_size) {
    const int* x         = (const int*)d_in[0];
    const float* emb     = (const float*)d_in[1];
    const float* eWih0   = (const float*)d_in[2];
    const float* eWhh0   = (const float*)d_in[3];
    const float* ebih0   = (const float*)d_in[4];
    const float* ebhh0   = (const float*)d_in[5];
    const float* eWih1   = (const float*)d_in[6];
    const float* eWhh1   = (const float*)d_in[7];
    const float* ebih1   = (const float*)d_in[8];
    const float* ebhh1   = (const float*)d_in[9];
    const float* dWih0   = (const float*)d_in[10];
    const float* dWhh0   = (const float*)d_in[11];
    const float* dbih0   = (const float*)d_in[12];
    const float* dbhh0   = (const float*)d_in[13];
    const float* dWih1   = (const float*)d_in[14];
    const float* dWhh1   = (const float*)d_in[15];
    const float* dbih1   = (const float*)d_in[16];
    const float* dbhh1   = (const float*)d_in[17];
    const float* fcW     = (const float*)d_in[18];
    const float* fcb     = (const float*)d_in[19];
    const float* recW    = (const float*)d_in[20];
    const float* recb    = (const float*)d_in[21];

    float* out = (float*)d_out;          // (64, 20)
    float* rec = out + 64 * 20;          // (64, 100, 10000)

    float *e, *gi, *y, *fcin, *fcin_tf, *wt, *recw;
    cudaGetSymbolAddress((void**)&e,       g_e);
    cudaGetSymbolAddress((void**)&gi,      g_gi);
    cudaGetSymbolAddress((void**)&y,       g_y);
    cudaGetSymbolAddress((void**)&fcin,    g_fcin);
    cudaGetSymbolAddress((void**)&fcin_tf, g_fcin_tf);
    cudaGetSymbolAddress((void**)&wt,      g_wt);
    cudaGetSymbolAddress((void**)&recw,    g_recw);

    cudaFuncSetAttribute(mma_tn, cudaFuncAttributeMaxDynamicSharedMemorySize, MMA_SMEM);

    dim3 gruGrid(BATCH, 2);

    // 0. pre-round all GEMM weights to tf32, one launch
    cvt_all<<<3364, 256>>>((const float4*)eWih0, (float4*)(wt + 0),
                           (const float4*)eWih1, (float4*)(wt + 98304),
                           (const float4*)dWih0, (float4*)(wt + 294912),
                           (const float4*)dWih1, (float4*)(wt + 688128),
                           (const float4*)recW,  (float4*)recw);

    // 1. embedding (tf32-rounded output)
    embed_kernel<<<6400, 128>>>(x, emb, e);

    // 2. encoder layer 0
    mma_tn<<<dim3(6, 50), 256, MMA_SMEM>>>(e, 128, wt + 0, ebih0, gi, 6400, 768, 128);
    gru_kernel<<<gruGrid, 768>>>(gi, TSEQ, 1, eWhh0, ebhh0, y, fcin + 0);

    // 3. encoder layer 1
    mma_tn<<<dim3(6, 50), 256, MMA_SMEM>>>(y, 256, wt + 98304, ebih1, gi, 6400, 768, 256);
    gru_kernel<<<gruGrid, 768>>>(gi, TSEQ, 1, eWhh1, ebhh1, y, fcin + 256);

    // 4. decoder layer 0 (constant input over T)
    cvt_kernel<<<64, 256>>>(fcin, fcin_tf, 65536);
    mma_tn<<<dim3(6, 1), 256, MMA_SMEM>>>(fcin_tf, 1024, wt + 294912, dbih0, gi, 64, 768, 512);
    gru_kernel<<<gruGrid, 768>>>(gi, 1, 0, dWhh0, dbhh0, y, fcin + 512);

    // 5. decoder layer 1 (output y = rec_seq)
    mma_tn<<<dim3(6, 50), 256, MMA_SMEM>>>(y, 256, wt + 688128, dbih1, gi, 6400, 768, 256);
    gru_kernel<<<gruGrid, 768>>>(gi, TSEQ, 1, dWhh1, dbhh1, y, fcin + 768);

    // 6. classifier head (fp32 GEMV, warp per output)
    fc_kernel<<<160, 256>>>(fcin, fcW, fcb, out);

    // 7. reconstruction: rec = rec_seq @ rec_W^T + rec_b
    mma_tn<<<dim3(79, 50), 256, MMA_SMEM>>>(y, 256, recw, recb, rec, 6400, 10000, 256);
}

// round 13
// speedup vs baseline: 1.2104x; 1.2104x over previous
#include <cuda_runtime.h>
#include <math.h>

#define TSEQ 100
#define BATCH 64
#define HGRU  128
#define G3    384   // 3*H

// ---------------- tf32 helpers ----------------
__device__ __forceinline__ unsigned f2tf32(float x) {
    unsigned u;
    asm("cvt.rna.tf32.f32 %0, %1;" : "=r"(u) : "f"(x));
    return u;
}

__device__ __forceinline__ void mma_tf32v(float* d, const unsigned* a, const unsigned* b) {
    asm volatile(
        "mma.sync.aligned.m16n8k8.row.col.f32.tf32.tf32.f32 "
        "{%0,%1,%2,%3}, {%4,%5,%6,%7}, {%8,%9}, {%0,%1,%2,%3};"
        : "+f"(d[0]), "+f"(d[1]), "+f"(d[2]), "+f"(d[3])
        : "r"(a[0]), "r"(a[1]), "r"(a[2]), "r"(a[3]),
          "r"(b[0]), "r"(b[1]));
}

// cp.async helpers
#define CPA(dst, src, sz) \
    asm volatile("cp.async.ca.shared.global [%0], [%1], 16, %2;" :: "r"(dst), "l"(src), "r"(sz))
#define CPC()  asm volatile("cp.async.commit_group;")
#define CPW0() asm volatile("cp.async.wait_group 0;")
#define CPW1() asm volatile("cp.async.wait_group 1;")

// ---------------- scratch (static __device__, no allocation) ----------------
__device__ float g_e[6400 * 128];      // embedded input, tf32-rounded
__device__ float g_gi[6400 * 768];     // gi for both directions (fp32)
__device__ float g_y[6400 * 256];      // layer output, tf32-rounded
__device__ float g_fcin[64 * 1024];    // [enc_h(512) | dec_h(512)], full fp32
__device__ float g_fcin_tf[64 * 1024]; // tf32-rounded copy for dec-l0 GEMM
__device__ float g_wt[884736];         // tf32 Wih: enc0@0, enc1@98304, dec0@294912, dec1@688128
__device__ float g_recw[2560000];      // tf32 recW

// ---------------- fused tf32 rounding of all 5 weight regions (one launch) ----------------
// float4 units: 24576 | 49152 | 98304 | 49152 | 640000, prefix: 24576,73728,172032,221184,861184
__global__ void cvt_all(const float4* __restrict__ s0, float4* __restrict__ d0,
                        const float4* __restrict__ s1, float4* __restrict__ d1,
                        const float4* __restrict__ s2, float4* __restrict__ d2,
                        const float4* __restrict__ s3, float4* __restrict__ d3,
                        const float4* __restrict__ s4, float4* __restrict__ d4) {
    int i = blockIdx.x * 256 + threadIdx.x;
    const float4* s; float4* d; int off;
    if      (i < 24576)  { s = s0; d = d0; off = i; }
    else if (i < 73728)  { s = s1; d = d1; off = i - 24576; }
    else if (i < 172032) { s = s2; d = d2; off = i - 73728; }
    else if (i < 221184) { s = s3; d = d3; off = i - 172032; }
    else if (i < 861184) { s = s4; d = d4; off = i - 221184; }
    else return;
    float4 v = s[off];
    v.x = __uint_as_float(f2tf32(v.x));
    v.y = __uint_as_float(f2tf32(v.y));
    v.z = __uint_as_float(f2tf32(v.z));
    v.w = __uint_as_float(f2tf32(v.w));
    d[off] = v;
}

// ---------------- elementwise tf32 rounding (fcin only) ----------------
__global__ void cvt_kernel(const float* __restrict__ src, float* __restrict__ dst, int n) {
    for (int i = blockIdx.x * 256 + threadIdx.x; i < n; i += gridDim.x * 256)
        dst[i] = __uint_as_float(f2tf32(src[i]));
}

// ---------------- embedding gather (writes tf32-rounded) ----------------
__global__ void embed_kernel(const int* __restrict__ x,
                             const float* __restrict__ emb,
                             float* __restrict__ e) {
    int row = blockIdx.x;                 // b*T + t
    int v = x[row];
    if (v > 9999) v = 9999;
    if (v < 0)    v = 0;
    e[row * 128 + threadIdx.x] = __uint_as_float(f2tf32(emb[v * 128 + threadIdx.x]));
}

// ---------------- classifier head GEMV: warp per output ----------------
__global__ void fc_kernel(const float* __restrict__ fcin,   // (64, 1024)
                          const float* __restrict__ W,      // (20, 1024)
                          const float* __restrict__ bias,   // (20)
                          float* __restrict__ out) {        // (64, 20)
    int wid  = (blockIdx.x * blockDim.x + threadIdx.x) >> 5;
    int lane = threadIdx.x & 31;
    if (wid >= 64 * 20) return;
    int m = wid / 20, n = wid % 20;
    const float4* a = (const float4*)(fcin + m * 1024);
    const float4* w = (const float4*)(W    + n * 1024);
    float s = 0.f;
#pragma unroll
    for (int i = lane; i < 256; i += 32) {
        float4 x = a[i], y = w[i];
        s += x.x * y.x + x.y * y.y + x.z * y.z + x.w * y.w;
    }
#pragma unroll
    for (int o = 16; o; o >>= 1) s += __shfl_xor_sync(0xffffffffu, s, o);
    if (lane == 0) out[m * 20 + n] = s + bias[n];
}

// ---------------- GRU recurrence (r11 version): packed f32x2 FMA, LDS.128 h-loads, gi prefetch ----------------
// h loads are COMPILER-VISIBLE shared reads so they cannot be hoisted across
// __syncthreads(); only the FMA is asm (inputs vary per iteration -> no CSE).
__global__ void __launch_bounds__(384, 1)
gru_kernel(const float* __restrict__ gi_base, int rb, int rt,
           const float* __restrict__ Whh,   // (2, 384, 128)
           const float* __restrict__ bhh,   // (2, 384)
           float* __restrict__ y,           // (B, T, 256), written tf32-rounded
           float* __restrict__ hfin) {
    __shared__ __align__(16) float sh[128];
    __shared__ float sgh[G3];
    __shared__ float sgi[G3];

    int j   = threadIdx.x;    // 0..383 (gate-column)
    int b   = blockIdx.x;
    int dir = blockIdx.y;

    const float* gi = gi_base + dir * G3;
    float bh = bhh[dir * G3 + j];

    // this column's Whh row (128 floats) as 64 packed f32x2 registers
    unsigned long long w2[64];
    const unsigned long long* Wrow =
        (const unsigned long long*)(Whh + (size_t)(dir * G3 + j) * HGRU);
#pragma unroll
    for (int kk = 0; kk < 64; kk++) w2[kk] = Wrow[kk];

    if (j < HGRU) sh[j] = 0.f;
    __syncthreads();

    const ulonglong2* sh2 = (const ulonglong2*)sh;   // 32 x 16B

    int tt_first = dir ? (TSEQ - 1) : 0;
    float gval = gi[(b * rb + tt_first * rt) * 768 + j];

    for (int t = 0; t < TSEQ; t++) {
        int tt = dir ? (TSEQ - 1 - t) : t;

        // prefetch next step's gi — consumed a full step later
        float gnext = 0.f;
        if (t + 1 < TSEQ) {
            int ttn = dir ? (TSEQ - 2 - t) : (t + 1);
            gnext = gi[(b * rb + ttn * rt) * 768 + j];
        }

        unsigned long long acc0 = 0ULL, acc1 = 0ULL, acc2 = 0ULL, acc3 = 0ULL;
#pragma unroll
        for (int kk = 0; kk < 32; kk += 2) {
            ulonglong2 ha = sh2[kk];
            ulonglong2 hb = sh2[kk + 1];
            asm("fma.rn.f32x2 %0, %1, %2, %0;" : "+l"(acc0) : "l"(w2[2 * kk + 0]), "l"(ha.x));
            asm("fma.rn.f32x2 %0, %1, %2, %0;" : "+l"(acc1) : "l"(w2[2 * kk + 1]), "l"(ha.y));
            asm("fma.rn.f32x2 %0, %1, %2, %0;" : "+l"(acc2) : "l"(w2[2 * kk + 2]), "l"(hb.x));
            asm("fma.rn.f32x2 %0, %1, %2, %0;" : "+l"(acc3) : "l"(w2[2 * kk + 3]), "l"(hb.y));
        }
        asm("add.rn.f32x2 %0, %0, %1;" : "+l"(acc0) : "l"(acc1));
        asm("add.rn.f32x2 %0, %0, %1;" : "+l"(acc2) : "l"(acc3));
        asm("add.rn.f32x2 %0, %0, %1;" : "+l"(acc0) : "l"(acc2));
        float lo, hi;
        asm("mov.b64 {%0,%1}, %2;" : "=f"(lo), "=f"(hi) : "l"(acc0));

        sgh[j] = lo + hi + bh;
        sgi[j] = gval;
        __syncthreads();

        if (j < HGRU) {
            float r = __fdividef(1.f, 1.f + __expf(-(sgi[j]        + sgh[j])));
            float z = __fdividef(1.f, 1.f + __expf(-(sgi[HGRU + j] + sgh[HGRU + j])));
            float nx = sgi[2 * HGRU + j] + r * sgh[2 * HGRU + j];
            float et = __expf(-2.f * nx);
            float n  = __fdividef(1.f - et, 1.f + et);   // tanh(nx)
            float hn = n + z * (sh[j] - n);
            sh[j] = hn;
            y[(b * TSEQ + tt) * 256 + dir * HGRU + j] = __uint_as_float(f2tf32(hn));
        }
        __syncthreads();

        gval = gnext;
    }
    if (j < HGRU) hfin[b * 1024 + dir * HGRU + j] = sh[j];
}

// ---------------- tf32 MMA GEMM, cp.async 3-stage, ONE barrier per K-chunk ----------------
// C[M,N] = A[M,K](lda) * W[N,K]^T + bias. Inputs MUST be pre-rounded to tf32.
// 128x128 CTA tile, 8 warps (4M x 2N), warp tile 32x64, K-chunk 32.
// Schedule per chunk ci: wait_group(1) -> sync -> stage(ci+2) -> compute(ci).
// stage at iter ci writes buf (ci+2)%3 == (ci-1)%3, which every warp finished
// computing before its sync this iteration -> safe with a single barrier.
#define MMA_STAGES 3
#define MMA_BUF    (128 * 36)                       // floats per operand per stage
#define MMA_SMEM   (MMA_STAGES * MMA_BUF * 4 * 2)   // 110592 B
__global__ void __launch_bounds__(256, 2)
mma_tn(const float* __restrict__ A, int lda,
       const float* __restrict__ W,     // (N, K)
       const float* __restrict__ bias,  // (N)
       float* __restrict__ C,
       int M, int N, int K) {
    extern __shared__ float smem[];
    float* As = smem;                        // [3][128][36]
    float* Bs = smem + MMA_STAGES * MMA_BUF;

    int t    = threadIdx.x;
    int lane = t & 31;
    int warp = t >> 5;
    int m0 = blockIdx.y * 128;
    int n0 = blockIdx.x * 128;
    int wm = (warp & 3) * 32;
    int wn = (warp >> 2) * 64;
    int r  = lane >> 2;       // 0..7
    int c  = lane & 3;        // 0..3

    unsigned sbaseA = (unsigned)__cvta_generic_to_shared(As);
    unsigned sbaseB = (unsigned)__cvta_generic_to_shared(Bs);

    float acc[2][8][4];
#pragma unroll
    for (int mf = 0; mf < 2; mf++)
#pragma unroll
        for (int nf = 0; nf < 8; nf++)
#pragma unroll
            for (int i = 0; i < 4; i++) acc[mf][nf][i] = 0.f;

    int nch = K >> 5;    // K/32 chunks

    auto stage = [&](int buf, int k0) {
#pragma unroll
        for (int i = 0; i < 4; i++) {
            int idx = i * 256 + t;
            int row = idx >> 3;
            int c4  = (idx & 7) * 4;
            unsigned off = ((unsigned)(buf * 128 + row) * 36 + c4) * 4;
            CPA(sbaseA + off, &A[(size_t)(m0 + row) * lda + k0 + c4], (m0 + row < M) ? 16 : 0);
            CPA(sbaseB + off, &W[(size_t)(n0 + row) * K   + k0 + c4], (n0 + row < N) ? 16 : 0);
        }
    };

    auto compute = [&](int buf) {
        const float* Ab = As + buf * MMA_BUF;
        const float* Bb = Bs + buf * MMA_BUF;
#pragma unroll
        for (int ks = 0; ks < 4; ks++) {
            int kb = ks * 8;
            unsigned a[2][4];
#pragma unroll
            for (int mf = 0; mf < 2; mf++) {
                int mr = wm + mf * 16 + r;
                a[mf][0] = __float_as_uint(Ab[(mr    ) * 36 + kb + c]);
                a[mf][1] = __float_as_uint(Ab[(mr + 8) * 36 + kb + c]);
                a[mf][2] = __float_as_uint(Ab[(mr    ) * 36 + kb + c + 4]);
                a[mf][3] = __float_as_uint(Ab[(mr + 8) * 36 + kb + c + 4]);
            }
#pragma unroll
            for (int nf = 0; nf < 8; nf++) {
                int nr = wn + nf * 8 + r;
                unsigned b[2];
                b[0] = __float_as_uint(Bb[nr * 36 + kb + c]);
                b[1] = __float_as_uint(Bb[nr * 36 + kb + c + 4]);
                mma_tf32v(acc[0][nf], a[0], b);
                mma_tf32v(acc[1][nf], a[1], b);
            }
        }
    };

    // prologue: 2 chunks in flight
    stage(0, 0);  CPC();
    if (nch > 1) { stage(1, 32); CPC(); }

    int buf = 0;            // buf == ci % 3, maintained by rotation
    for (int ci = 0; ci < nch; ci++) {
        if (ci < nch - 1) { CPW1(); } else { CPW0(); }
        __syncthreads();
        if (ci + 2 < nch) {
            int nb = buf + 2; if (nb >= 3) nb -= 3;
            stage(nb, (ci + 2) * 32); CPC();
        }
        compute(buf);
        if (++buf == 3) buf = 0;
    }

    // epilogue
#pragma unroll
    for (int mf = 0; mf < 2; mf++) {
#pragma unroll
        for (int nf = 0; nf < 8; nf++) {
            int n = n0 + wn + nf * 8 + 2 * c;
            if (n >= N) continue;
            float bv0 = bias[n];
            float bv1 = bias[n + 1];
            int m = m0 + wm + mf * 16 + r;
            if (m < M) {
                *(float2*)&C[(size_t)m * N + n] =
                    make_float2(acc[mf][nf][0] + bv0, acc[mf][nf][1] + bv1);
            }
            if (m + 8 < M) {
                *(float2*)&C[(size_t)(m + 8) * N + n] =
                    make_float2(acc[mf][nf][2] + bv0, acc[mf][nf][3] + bv1);
            }
        }
    }
}

// ---------------- driver ----------------
extern "C" void kernel_launch(void* const* d_in, const int* in_sizes, int n_in,
                              void* d_out, int out_size) {
    const int* x         = (const int*)d_in[0];
    const float* emb     = (const float*)d_in[1];
    const float* eWih0   = (const float*)d_in[2];
    const float* eWhh0   = (const float*)d_in[3];
    const float* ebih0   = (const float*)d_in[4];
    const float* ebhh0   = (const float*)d_in[5];
    const float* eWih1   = (const float*)d_in[6];
    const float* eWhh1   = (const float*)d_in[7];
    const float* ebih1   = (const float*)d_in[8];
    const float* ebhh1   = (const float*)d_in[9];
    const float* dWih0   = (const float*)d_in[10];
    const float* dWhh0   = (const float*)d_in[11];
    const float* dbih0   = (const float*)d_in[12];
    const float* dbhh0   = (const float*)d_in[13];
    const float* dWih1   = (const float*)d_in[14];
    const float* dWhh1   = (const float*)d_in[15];
    const float* dbih1   = (const float*)d_in[16];
    const float* dbhh1   = (const float*)d_in[17];
    const float* fcW     = (const float*)d_in[18];
    const float* fcb     = (const float*)d_in[19];
    const float* recW    = (const float*)d_in[20];
    const float* recb    = (const float*)d_in[21];

    float* out = (float*)d_out;          // (64, 20)
    float* rec = out + 64 * 20;          // (64, 100, 10000)

    float *e, *gi, *y, *fcin, *fcin_tf, *wt, *recw;
    cudaGetSymbolAddress((void**)&e,       g_e);
    cudaGetSymbolAddress((void**)&gi,      g_gi);
    cudaGetSymbolAddress((void**)&y,       g_y);
    cudaGetSymbolAddress((void**)&fcin,    g_fcin);
    cudaGetSymbolAddress((void**)&fcin_tf, g_fcin_tf);
    cudaGetSymbolAddress((void**)&wt,      g_wt);
    cudaGetSymbolAddress((void**)&recw,    g_recw);

    cudaFuncSetAttribute(mma_tn, cudaFuncAttributeMaxDynamicSharedMemorySize, MMA_SMEM);

    dim3 gruGrid(BATCH, 2);

    // 0. pre-round all GEMM weights to tf32, one launch
    cvt_all<<<3364, 256>>>((const float4*)eWih0, (float4*)(wt + 0),
                           (const float4*)eWih1, (float4*)(wt + 98304),
                           (const float4*)dWih0, (float4*)(wt + 294912),
                           (const float4*)dWih1, (float4*)(wt + 688128),
                           (const float4*)recW,  (float4*)recw);

    // 1. embedding (tf32-rounded output)
    embed_kernel<<<6400, 128>>>(x, emb, e);

    // 2. encoder layer 0
    mma_tn<<<dim3(6, 50), 256, MMA_SMEM>>>(e, 128, wt + 0, ebih0, gi, 6400, 768, 128);
    gru_kernel<<<gruGrid, 384>>>(gi, TSEQ, 1, eWhh0, ebhh0, y, fcin + 0);

    // 3. encoder layer 1
    mma_tn<<<dim3(6, 50), 256, MMA_SMEM>>>(y, 256, wt + 98304, ebih1, gi, 6400, 768, 256);
    gru_kernel<<<gruGrid, 384>>>(gi, TSEQ, 1, eWhh1, ebhh1, y, fcin + 256);

    // 4. decoder layer 0 (constant input over T)
    cvt_kernel<<<64, 256>>>(fcin, fcin_tf, 65536);
    mma_tn<<<dim3(6, 1), 256, MMA_SMEM>>>(fcin_tf, 1024, wt + 294912, dbih0, gi, 64, 768, 512);
    gru_kernel<<<gruGrid, 384>>>(gi, 1, 0, dWhh0, dbhh0, y, fcin + 512);

    // 5. decoder layer 1 (output y = rec_seq)
    mma_tn<<<dim3(6, 50), 256, MMA_SMEM>>>(y, 256, wt + 688128, dbih1, gi, 6400, 768, 256);
    gru_kernel<<<gruGrid, 384>>>(gi, TSEQ, 1, dWhh1, dbhh1, y, fcin + 768);

    // 6. classifier head (fp32 GEMV, warp per output)
    fc_kernel<<<160, 256>>>(fcin, fcW, fcb, out);

    // 7. reconstruction: rec = rec_seq @ rec_W^T + rec_b
    mma_tn<<<dim3(79, 50), 256, MMA_SMEM>>>(y, 256, recw, recb, rec, 6400, 10000, 256);
}

// round 14
// speedup vs baseline: 1.2156x; 1.0043x over previous
#include <cuda_runtime.h>
#include <math.h>

#define TSEQ 100
#define BATCH 64
#define HGRU  128
#define G3    384   // 3*H

// ---------------- tf32 helpers ----------------
__device__ __forceinline__ unsigned f2tf32(float x) {
    unsigned u;
    asm("cvt.rna.tf32.f32 %0, %1;" : "=r"(u) : "f"(x));
    return u;
}

__device__ __forceinline__ void mma_tf32v(float* d, const unsigned* a, const unsigned* b) {
    asm volatile(
        "mma.sync.aligned.m16n8k8.row.col.f32.tf32.tf32.f32 "
        "{%0,%1,%2,%3}, {%4,%5,%6,%7}, {%8,%9}, {%0,%1,%2,%3};"
        : "+f"(d[0]), "+f"(d[1]), "+f"(d[2]), "+f"(d[3])
        : "r"(a[0]), "r"(a[1]), "r"(a[2]), "r"(a[3]),
          "r"(b[0]), "r"(b[1]));
}

// cp.async helpers
#define CPA(dst, src, sz) \
    asm volatile("cp.async.ca.shared.global [%0], [%1], 16, %2;" :: "r"(dst), "l"(src), "r"(sz))
#define CPC()  asm volatile("cp.async.commit_group;")
#define CPW0() asm volatile("cp.async.wait_group 0;")
#define CPW1() asm volatile("cp.async.wait_group 1;")

// ---------------- scratch (static __device__, no allocation) ----------------
__device__ float g_e[6400 * 128];      // embedded input, tf32-rounded
__device__ float g_gi[6400 * 768];     // gi for both directions (fp32)
__device__ float g_y[6400 * 256];      // layer output, tf32-rounded
__device__ float g_fcin[64 * 1024];    // [enc_h(512) | dec_h(512)], full fp32
__device__ float g_fcin_tf[64 * 1024]; // tf32-rounded copy for dec-l0 GEMM
__device__ float g_wt[884736];         // tf32 Wih: enc0@0, enc1@98304, dec0@294912, dec1@688128
__device__ float g_recw[2560000];      // tf32 recW

// ---------------- fused tf32 rounding of all 5 weight regions (one launch) ----------------
// float4 units: 24576 | 49152 | 98304 | 49152 | 640000, prefix: 24576,73728,172032,221184,861184
__global__ void cvt_all(const float4* __restrict__ s0, float4* __restrict__ d0,
                        const float4* __restrict__ s1, float4* __restrict__ d1,
                        const float4* __restrict__ s2, float4* __restrict__ d2,
                        const float4* __restrict__ s3, float4* __restrict__ d3,
                        const float4* __restrict__ s4, float4* __restrict__ d4) {
    int i = blockIdx.x * 256 + threadIdx.x;
    const float4* s; float4* d; int off;
    if      (i < 24576)  { s = s0; d = d0; off = i; }
    else if (i < 73728)  { s = s1; d = d1; off = i - 24576; }
    else if (i < 172032) { s = s2; d = d2; off = i - 73728; }
    else if (i < 221184) { s = s3; d = d3; off = i - 172032; }
    else if (i < 861184) { s = s4; d = d4; off = i - 221184; }
    else return;
    float4 v = s[off];
    v.x = __uint_as_float(f2tf32(v.x));
    v.y = __uint_as_float(f2tf32(v.y));
    v.z = __uint_as_float(f2tf32(v.z));
    v.w = __uint_as_float(f2tf32(v.w));
    d[off] = v;
}

// ---------------- elementwise tf32 rounding (fcin only) ----------------
__global__ void cvt_kernel(const float* __restrict__ src, float* __restrict__ dst, int n) {
    for (int i = blockIdx.x * 256 + threadIdx.x; i < n; i += gridDim.x * 256)
        dst[i] = __uint_as_float(f2tf32(src[i]));
}

// ---------------- embedding gather (writes tf32-rounded) ----------------
__global__ void embed_kernel(const int* __restrict__ x,
                             const float* __restrict__ emb,
                             float* __restrict__ e) {
    int row = blockIdx.x;                 // b*T + t
    int v = x[row];
    if (v > 9999) v = 9999;
    if (v < 0)    v = 0;
    e[row * 128 + threadIdx.x] = __uint_as_float(f2tf32(emb[v * 128 + threadIdx.x]));
}

// ---------------- classifier head GEMV: warp per output ----------------
__global__ void fc_kernel(const float* __restrict__ fcin,   // (64, 1024)
                          const float* __restrict__ W,      // (20, 1024)
                          const float* __restrict__ bias,   // (20)
                          float* __restrict__ out) {        // (64, 20)
    int wid  = (blockIdx.x * blockDim.x + threadIdx.x) >> 5;
    int lane = threadIdx.x & 31;
    if (wid >= 64 * 20) return;
    int m = wid / 20, n = wid % 20;
    const float4* a = (const float4*)(fcin + m * 1024);
    const float4* w = (const float4*)(W    + n * 1024);
    float s = 0.f;
#pragma unroll
    for (int i = lane; i < 256; i += 32) {
        float4 x = a[i], y = w[i];
        s += x.x * y.x + x.y * y.y + x.z * y.z + x.w * y.w;
    }
#pragma unroll
    for (int o = 16; o; o >>= 1) s += __shfl_xor_sync(0xffffffffu, s, o);
    if (lane == 0) out[m * 20 + n] = s + bias[n];
}

// ---------------- GRU recurrence (r11 version): packed f32x2 FMA, LDS.128 h-loads, gi prefetch ----------------
// h loads are COMPILER-VISIBLE shared reads so they cannot be hoisted across
// __syncthreads(); only the FMA is asm (inputs vary per iteration -> no CSE).
__global__ void __launch_bounds__(384, 1)
gru_kernel(const float* __restrict__ gi_base, int rb, int rt,
           const float* __restrict__ Whh,   // (2, 384, 128)
           const float* __restrict__ bhh,   // (2, 384)
           float* __restrict__ y,           // (B, T, 256), written tf32-rounded
           float* __restrict__ hfin) {
    __shared__ __align__(16) float sh[128];
    __shared__ float sgh[G3];
    __shared__ float sgi[G3];

    int j   = threadIdx.x;    // 0..383 (gate-column)
    int b   = blockIdx.x;
    int dir = blockIdx.y;

    const float* gi = gi_base + dir * G3;
    float bh = bhh[dir * G3 + j];

    // this column's Whh row (128 floats) as 64 packed f32x2 registers
    unsigned long long w2[64];
    const unsigned long long* Wrow =
        (const unsigned long long*)(Whh + (size_t)(dir * G3 + j) * HGRU);
#pragma unroll
    for (int kk = 0; kk < 64; kk++) w2[kk] = Wrow[kk];

    if (j < HGRU) sh[j] = 0.f;
    __syncthreads();

    const ulonglong2* sh2 = (const ulonglong2*)sh;   // 32 x 16B

    int tt_first = dir ? (TSEQ - 1) : 0;
    float gval = gi[(b * rb + tt_first * rt) * 768 + j];

    for (int t = 0; t < TSEQ; t++) {
        int tt = dir ? (TSEQ - 1 - t) : t;

        // prefetch next step's gi — consumed a full step later
        float gnext = 0.f;
        if (t + 1 < TSEQ) {
            int ttn = dir ? (TSEQ - 2 - t) : (t + 1);
            gnext = gi[(b * rb + ttn * rt) * 768 + j];
        }

        unsigned long long acc0 = 0ULL, acc1 = 0ULL, acc2 = 0ULL, acc3 = 0ULL;
#pragma unroll
        for (int kk = 0; kk < 32; kk += 2) {
            ulonglong2 ha = sh2[kk];
            ulonglong2 hb = sh2[kk + 1];
            asm("fma.rn.f32x2 %0, %1, %2, %0;" : "+l"(acc0) : "l"(w2[2 * kk + 0]), "l"(ha.x));
            asm("fma.rn.f32x2 %0, %1, %2, %0;" : "+l"(acc1) : "l"(w2[2 * kk + 1]), "l"(ha.y));
            asm("fma.rn.f32x2 %0, %1, %2, %0;" : "+l"(acc2) : "l"(w2[2 * kk + 2]), "l"(hb.x));
            asm("fma.rn.f32x2 %0, %1, %2, %0;" : "+l"(acc3) : "l"(w2[2 * kk + 3]), "l"(hb.y));
        }
        asm("add.rn.f32x2 %0, %0, %1;" : "+l"(acc0) : "l"(acc1));
        asm("add.rn.f32x2 %0, %0, %1;" : "+l"(acc2) : "l"(acc3));
        asm("add.rn.f32x2 %0, %0, %1;" : "+l"(acc0) : "l"(acc2));
        float lo, hi;
        asm("mov.b64 {%0,%1}, %2;" : "=f"(lo), "=f"(hi) : "l"(acc0));

        sgh[j] = lo + hi + bh;
        sgi[j] = gval;
        __syncthreads();

        if (j < HGRU) {
            float r = __fdividef(1.f, 1.f + __expf(-(sgi[j]        + sgh[j])));
            float z = __fdividef(1.f, 1.f + __expf(-(sgi[HGRU + j] + sgh[HGRU + j])));
            float nx = sgi[2 * HGRU + j] + r * sgh[2 * HGRU + j];
            float et = __expf(-2.f * nx);
            float n  = __fdividef(1.f - et, 1.f + et);   // tanh(nx)
            float hn = n + z * (sh[j] - n);
            sh[j] = hn;
            y[(b * TSEQ + tt) * 256 + dir * HGRU + j] = __uint_as_float(f2tf32(hn));
        }
        __syncthreads();

        gval = gnext;
    }
    if (j < HGRU) hfin[b * 1024 + dir * HGRU + j] = sh[j];
}

// ---------------- tf32 MMA GEMM, cp.async 3-stage + ldmatrix fragment loads ----------------
// C[M,N] = A[M,K](lda) * W[N,K]^T + bias. Inputs MUST be pre-rounded to tf32.
// 128x128 CTA tile, 8 warps (4M x 2N), warp tile 32x64, K-chunk 32.
// ldmatrix.m8n8.x4.b16 on 4-byte data: reg t of lane l = tile_t[l>>2][l&3] (one f32),
// which is exactly the m16n8k8 tf32 fragment mapping. Stride-36 rows stay 16B-aligned
// and conflict-free (row q of a tile covers banks 4q..4q+3).
#define MMA_STAGES 3
#define MMA_BUF    (128 * 36)                       // floats per operand per stage
#define MMA_SMEM   (MMA_STAGES * MMA_BUF * 4 * 2)   // 110592 B
__global__ void __launch_bounds__(256, 2)
mma_tn(const float* __restrict__ A, int lda,
       const float* __restrict__ W,     // (N, K)
       const float* __restrict__ bias,  // (N)
       float* __restrict__ C,
       int M, int N, int K) {
    extern __shared__ float smem[];
    float* As = smem;                        // [3][128][36]
    float* Bs = smem + MMA_STAGES * MMA_BUF;

    int t    = threadIdx.x;
    int lane = t & 31;
    int warp = t >> 5;
    int m0 = blockIdx.y * 128;
    int n0 = blockIdx.x * 128;
    int wm = (warp & 3) * 32;
    int wn = (warp >> 2) * 64;
    int r  = lane >> 2;       // 0..7
    int c  = lane & 3;        // 0..3

    unsigned sbaseA = (unsigned)__cvta_generic_to_shared(As);
    unsigned sbaseB = (unsigned)__cvta_generic_to_shared(Bs);

    // lane-constant ldmatrix address parts
    int grp = lane >> 3, q = lane & 7;
    // A tiles: g0=(rows+0,col+0) g1=(rows+8,col+0) g2=(rows+0,col+4) g3=(rows+8,col+4)
    unsigned LA = (((unsigned)((grp & 1) * 8 + q)) * 36 + (unsigned)((grp >> 1) * 4)) * 4;
    // B tiles: g0=(nfblk+0,col+0) g1=(nfblk+0,col+4) g2=(nfblk+8,col+0) g3=(nfblk+8,col+4)
    unsigned LB = (((unsigned)((grp >> 1) * 8 + q)) * 36 + (unsigned)((grp & 1) * 4)) * 4;

    float acc[2][8][4];
#pragma unroll
    for (int mf = 0; mf < 2; mf++)
#pragma unroll
        for (int nf = 0; nf < 8; nf++)
#pragma unroll
            for (int i = 0; i < 4; i++) acc[mf][nf][i] = 0.f;

    int nch = K >> 5;    // K/32 chunks

    auto stage = [&](int buf, int k0) {
#pragma unroll
        for (int i = 0; i < 4; i++) {
            int idx = i * 256 + t;
            int row = idx >> 3;
            int c4  = (idx & 7) * 4;
            unsigned off = ((unsigned)(buf * 128 + row) * 36 + c4) * 4;
            CPA(sbaseA + off, &A[(size_t)(m0 + row) * lda + k0 + c4], (m0 + row < M) ? 16 : 0);
            CPA(sbaseB + off, &W[(size_t)(n0 + row) * K   + k0 + c4], (n0 + row < N) ? 16 : 0);
        }
    };

    auto compute = [&](int buf) {
        unsigned aB = sbaseA + (unsigned)buf * (MMA_BUF * 4);
        unsigned bB = sbaseB + (unsigned)buf * (MMA_BUF * 4);
#pragma unroll
        for (int ks = 0; ks < 4; ks++) {
            int kb = ks * 8;
            unsigned a[2][4];
#pragma unroll
            for (int mf = 0; mf < 2; mf++) {
                unsigned addr = aB + ((unsigned)((wm + mf * 16) * 36 + kb)) * 4 + LA;
                asm volatile(
                    "ldmatrix.sync.aligned.m8n8.x4.shared.b16 {%0,%1,%2,%3}, [%4];"
                    : "=r"(a[mf][0]), "=r"(a[mf][1]), "=r"(a[mf][2]), "=r"(a[mf][3])
                    : "r"(addr));
            }
#pragma unroll
            for (int p = 0; p < 4; p++) {
                unsigned b[4];   // {nf=2p: b0,b1, nf=2p+1: b0,b1}
                unsigned addr = bB + ((unsigned)((wn + 16 * p) * 36 + kb)) * 4 + LB;
                asm volatile(
                    "ldmatrix.sync.aligned.m8n8.x4.shared.b16 {%0,%1,%2,%3}, [%4];"
                    : "=r"(b[0]), "=r"(b[1]), "=r"(b[2]), "=r"(b[3])
                    : "r"(addr));
                mma_tf32v(acc[0][2 * p],     a[0], b);
                mma_tf32v(acc[1][2 * p],     a[1], b);
                mma_tf32v(acc[0][2 * p + 1], a[0], b + 2);
                mma_tf32v(acc[1][2 * p + 1], a[1], b + 2);
            }
        }
    };

    // prologue: 2 chunks in flight
    stage(0, 0);  CPC();
    if (nch > 1) { stage(1, 32); CPC(); }

    int buf = 0;            // buf == ci % 3, maintained by rotation
    for (int ci = 0; ci < nch; ci++) {
        if (ci < nch - 1) { CPW1(); } else { CPW0(); }
        __syncthreads();
        if (ci + 2 < nch) {
            int nb = buf + 2; if (nb >= 3) nb -= 3;
            stage(nb, (ci + 2) * 32); CPC();
        }
        compute(buf);
        if (++buf == 3) buf = 0;
    }

    // epilogue
#pragma unroll
    for (int mf = 0; mf < 2; mf++) {
#pragma unroll
        for (int nf = 0; nf < 8; nf++) {
            int n = n0 + wn + nf * 8 + 2 * c;
            if (n >= N) continue;
            float bv0 = bias[n];
            float bv1 = bias[n + 1];
            int m = m0 + wm + mf * 16 + r;
            if (m < M) {
                *(float2*)&C[(size_t)m * N + n] =
                    make_float2(acc[mf][nf][0] + bv0, acc[mf][nf][1] + bv1);
            }
            if (m + 8 < M) {
                *(float2*)&C[(size_t)(m + 8) * N + n] =
                    make_float2(acc[mf][nf][2] + bv0, acc[mf][nf][3] + bv1);
            }
        }
    }
}

// ---------------- driver ----------------
extern "C" void kernel_launch(void* const* d_in, const int* in_sizes, int n_in,
                              void* d_out, int out_size) {
    const int* x         = (const int*)d_in[0];
    const float* emb     = (const float*)d_in[1];
    const float* eWih0   = (const float*)d_in[2];
    const float* eWhh0   = (const float*)d_in[3];
    const float* ebih0   = (const float*)d_in[4];
    const float* ebhh0   = (const float*)d_in[5];
    const float* eWih1   = (const float*)d_in[6];
    const float* eWhh1   = (const float*)d_in[7];
    const float* ebih1   = (const float*)d_in[8];
    const float* ebhh1   = (const float*)d_in[9];
    const float* dWih0   = (const float*)d_in[10];
    const float* dWhh0   = (const float*)d_in[11];
    const float* dbih0   = (const float*)d_in[12];
    const float* dbhh0   = (const float*)d_in[13];
    const float* dWih1   = (const float*)d_in[14];
    const float* dWhh1   = (const float*)d_in[15];
    const float* dbih1   = (const float*)d_in[16];
    const float* dbhh1   = (const float*)d_in[17];
    const float* fcW     = (const float*)d_in[18];
    const float* fcb     = (const float*)d_in[19];
    const float* recW    = (const float*)d_in[20];
    const float* recb    = (const float*)d_in[21];

    float* out = (float*)d_out;          // (64, 20)
    float* rec = out + 64 * 20;          // (64, 100, 10000)

    float *e, *gi, *y, *fcin, *fcin_tf, *wt, *recw;
    cudaGetSymbolAddress((void**)&e,       g_e);
    cudaGetSymbolAddress((void**)&gi,      g_gi);
    cudaGetSymbolAddress((void**)&y,       g_y);
    cudaGetSymbolAddress((void**)&fcin,    g_fcin);
    cudaGetSymbolAddress((void**)&fcin_tf, g_fcin_tf);
    cudaGetSymbolAddress((void**)&wt,      g_wt);
    cudaGetSymbolAddress((void**)&recw,    g_recw);

    cudaFuncSetAttribute(mma_tn, cudaFuncAttributeMaxDynamicSharedMemorySize, MMA_SMEM);

    dim3 gruGrid(BATCH, 2);

    // 0. pre-round all GEMM weights to tf32, one launch
    cvt_all<<<3364, 256>>>((const float4*)eWih0, (float4*)(wt + 0),
                           (const float4*)eWih1, (float4*)(wt + 98304),
                           (const float4*)dWih0, (float4*)(wt + 294912),
                           (const float4*)dWih1, (float4*)(wt + 688128),
                           (const float4*)recW,  (float4*)recw);

    // 1. embedding (tf32-rounded output)
    embed_kernel<<<6400, 128>>>(x, emb, e);

    // 2. encoder layer 0
    mma_tn<<<dim3(6, 50), 256, MMA_SMEM>>>(e, 128, wt + 0, ebih0, gi, 6400, 768, 128);
    gru_kernel<<<gruGrid, 384>>>(gi, TSEQ, 1, eWhh0, ebhh0, y, fcin + 0);

    // 3. encoder layer 1
    mma_tn<<<dim3(6, 50), 256, MMA_SMEM>>>(y, 256, wt + 98304, ebih1, gi, 6400, 768, 256);
    gru_kernel<<<gruGrid, 384>>>(gi, TSEQ, 1, eWhh1, ebhh1, y, fcin + 256);

    // 4. decoder layer 0 (constant input over T)
    cvt_kernel<<<64, 256>>>(fcin, fcin_tf, 65536);
    mma_tn<<<dim3(6, 1), 256, MMA_SMEM>>>(fcin_tf, 1024, wt + 294912, dbih0, gi, 64, 768, 512);
    gru_kernel<<<gruGrid, 384>>>(gi, 1, 0, dWhh0, dbhh0, y, fcin + 512);

    // 5. decoder layer 1 (output y = rec_seq)
    mma_tn<<<dim3(6, 50), 256, MMA_SMEM>>>(y, 256, wt + 688128, dbih1, gi, 6400, 768, 256);
    gru_kernel<<<gruGrid, 384>>>(gi, TSEQ, 1, dWhh1, dbhh1, y, fcin + 768);

    // 6. classifier head (fp32 GEMV, warp per output)
    fc_kernel<<<160, 256>>>(fcin, fcW, fcb, out);

    // 7. reconstruction: rec = rec_seq @ rec_W^T + rec_b
    mma_tn<<<dim3(79, 50), 256, MMA_SMEM>>>(y, 256, recw, recb, rec, 6400, 10000, 256);
}